// round 9
// baseline (speedup 1.0000x reference)
#include <cuda_runtime.h>
#include <math.h>
#include <stdint.h>

// Problem constants
#define BB   8
#define SEQL 4096
#define QL   1024
#define CIN  256
#define KVD  640
#define QD   128
#define HH   8
#define KD   16
#define VD   64
#define COUT 512
#define EPSB 1e-3f

typedef unsigned long long ull;

// Intermediates as __device__ globals (no dynamic allocation allowed)
__device__ float d_kvbuf[BB * SEQL * KVD];   // [B, SEQ, 640]  (BN folded)
__device__ float d_qbuf [BB * QL * QD];      // [B, QLEN, 128] (BN folded)
__device__ float d_zbuf [BB * QL * COUT];    // [B, 1024, 512] attention out, TF-reshaped
__device__ float d_Wkvf[CIN * KVD];
__device__ float d_bkvf[KVD];
__device__ float d_Wqf [CIN * QD];
__device__ float d_bqf [QD];
__device__ float d_Wpf [COUT * COUT];
__device__ float d_bpf [COUT];

__device__ __forceinline__ float ex2(float x) {
    float y;
    asm("ex2.approx.ftz.f32 %0, %1;" : "=f"(y) : "f"(x));
    return y;
}
__device__ __forceinline__ uint32_t s2u(const void* p) {
    return (uint32_t)__cvta_generic_to_shared(p);
}
__device__ __forceinline__ void cpasync16(uint32_t dst, const void* src) {
    asm volatile("cp.async.cg.shared.global [%0], [%1], 16;" :: "r"(dst), "l"(src));
}
#define CP_COMMIT() asm volatile("cp.async.commit_group;")
#define CP_WAIT1()  asm volatile("cp.async.wait_group 1;")

// tf32 round-to-nearest conversion (f32 bit pattern, low 13 bits zero)
__device__ __forceinline__ uint32_t f2tf32(float x) {
    uint32_t r;
    asm("cvt.rna.tf32.f32 %0, %1;" : "=r"(r) : "f"(x));
    return r;
}
__device__ __forceinline__ float tf32r(float x) {
    return __uint_as_float(f2tf32(x));
}
// m16n8k8 tf32 MMA, D = A*B + D
__device__ __forceinline__ void mma_tf32(float& c0, float& c1, float& c2, float& c3,
                                         uint32_t a0, uint32_t a1, uint32_t a2, uint32_t a3,
                                         uint32_t b0, uint32_t b1) {
    asm volatile("mma.sync.aligned.m16n8k8.row.col.f32.tf32.tf32.f32 "
                 "{%0,%1,%2,%3}, {%4,%5,%6,%7}, {%8,%9}, {%0,%1,%2,%3};"
                 : "+f"(c0), "+f"(c1), "+f"(c2), "+f"(c3)
                 : "r"(a0), "r"(a1), "r"(a2), "r"(a3), "r"(b0), "r"(b1));
}

__device__ __forceinline__ float hswish(float x) {
    return x * __saturatef(x * (1.0f / 6.0f) + 0.5f);
}

// ---------------------------------------------------------------------------
// Fold BN into weights + bias.
// ---------------------------------------------------------------------------
template <int WHICH>
__global__ void fold_kernel(const float* __restrict__ W, const float* __restrict__ b,
                            const float* __restrict__ gam, const float* __restrict__ bet,
                            const float* __restrict__ mu, const float* __restrict__ var,
                            int K, int N) {
    float* Wf; float* bf;
    if (WHICH == 0)      { Wf = d_Wkvf; bf = d_bkvf; }
    else if (WHICH == 1) { Wf = d_Wqf;  bf = d_bqf;  }
    else                 { Wf = d_Wpf;  bf = d_bpf;  }
    int i = blockIdx.x * 256 + threadIdx.x;
    if (i < K * N) {
        int n = i % N;
        float s = gam[n] * rsqrtf(var[n] + EPSB);
        Wf[i] = W[i] * s;
    }
    if (i < N) {
        float s = gam[i] * rsqrtf(var[i] + EPSB);
        bf[i] = (b[i] - mu[i]) * s + bet[i];
    }
}

// ---------------------------------------------------------------------------
// tf32 tensor-core GEMM, cp.async double-buffered: C = f(A) @ W + bias.
// BM=128, BN=128, BK=16, 256 threads (8 warps: 4m x 2n, warp tile 32x64).
// Raw fp32 tiles in smem (A as [m][k], pad 20; B as [k][n], pad 132) — both
// fragment-LDS conflict-free. MODE 0/1: raw fp32 into mma (hw tf32 truncate).
// THREE=1 (proj): hi/lo split computed in registers at fragment load
// (hi*hi + hi*lo + lo*hi) for fp32-grade accuracy.
// MODE 0: kv (A=x), 1: q (A=x strided gather), 2: proj (A=hswish(zbuf)).
// ---------------------------------------------------------------------------
template <int MODE, int THREE>
__global__ __launch_bounds__(256, 2) void tgemm_kernel(const float* __restrict__ Ain,
                                                       float* __restrict__ Cout,
                                                       int M, int N, int K) {
    const float* W;  const float* bias;  float* C;  const float* A = Ain;
    if (MODE == 0)      { W = d_Wkvf; bias = d_bkvf; C = d_kvbuf; }
    else if (MODE == 1) { W = d_Wqf;  bias = d_bqf;  C = d_qbuf;  }
    else                { W = d_Wpf;  bias = d_bpf;  C = Cout; A = d_zbuf; }

    __shared__ __align__(16) float As[2][128][20];   // [m][k], 4-pad
    __shared__ __align__(16) float Bs[2][16][132];   // [k][n], 4-pad

    int tid  = threadIdx.x;
    int m0 = blockIdx.y * 128;
    int n0 = blockIdx.x * 128;
    int w = tid >> 5, lane = tid & 31;
    int g = lane >> 2, tg = lane & 3;
    int wm = w >> 1, wn = w & 1;           // warp tile: rows wm*32+, cols wn*64+

    float acc[2][8][4];
#pragma unroll
    for (int i = 0; i < 2; i++)
#pragma unroll
        for (int j = 0; j < 8; j++)
#pragma unroll
            for (int e = 0; e < 4; e++) acc[i][j][e] = 0.0f;

    // A-load: 2 16B chunks per thread (128 rows x 16 cols)
    int lrow[2], lc4[2];
    const float* aptr[2];
#pragma unroll
    for (int j = 0; j < 2; j++) {
        int idx = tid + j * 256;
        int r = idx >> 2, c4 = idx & 3;
        lrow[j] = r; lc4[j] = c4;
        int gr = m0 + r;
        int src;
        if (MODE == 1) {
            int bb = gr >> 10, ql = gr & 1023;
            int qy = ql >> 5, qx = ql & 31;
            src = (bb << 12) + (qy << 7) + (qx << 1);
        } else {
            src = gr;
        }
        aptr[j] = A + (size_t)src * K + c4 * 4;
    }
    // B-load: 2 16B chunks per thread (16 rows x 128 cols)
    int bkr[2], bnc[2];
    const float* bptr[2];
#pragma unroll
    for (int j = 0; j < 2; j++) {
        int idx = tid + j * 256;
        bkr[j] = idx >> 5; bnc[j] = (idx & 31) * 4;
        bptr[j] = W + (size_t)bkr[j] * N + n0 + bnc[j];
    }

    // prefetch tile 0
#pragma unroll
    for (int j = 0; j < 2; j++) {
        cpasync16(s2u(&As[0][lrow[j]][lc4[j] * 4]), aptr[j]);
        cpasync16(s2u(&Bs[0][bkr[j]][bnc[j]]), bptr[j]);
    }
    CP_COMMIT();

    const int NT = K / 16;
    for (int t = 0; t < NT; ++t) {
        if (t + 1 < NT) {
            int nb = (t + 1) & 1;
            int k0 = (t + 1) * 16;
#pragma unroll
            for (int j = 0; j < 2; j++) {
                cpasync16(s2u(&As[nb][lrow[j]][lc4[j] * 4]), aptr[j] + k0);
                cpasync16(s2u(&Bs[nb][bkr[j]][bnc[j]]), bptr[j] + (size_t)k0 * N);
            }
        }
        CP_COMMIT();
        CP_WAIT1();
        __syncthreads();

        const int bf = t & 1;
#pragma unroll
        for (int k8 = 0; k8 < 16; k8 += 8) {
            uint32_t ah[2][4], al[2][4];
#pragma unroll
            for (int mi = 0; mi < 2; mi++) {
                int r = wm * 32 + mi * 16 + g;
                float v0 = As[bf][r][k8 + tg];
                float v1 = As[bf][r + 8][k8 + tg];
                float v2 = As[bf][r][k8 + tg + 4];
                float v3 = As[bf][r + 8][k8 + tg + 4];
                if (MODE == 2) { v0 = hswish(v0); v1 = hswish(v1); v2 = hswish(v2); v3 = hswish(v3); }
                if (THREE) {
                    float h0 = tf32r(v0), h1 = tf32r(v1), h2 = tf32r(v2), h3 = tf32r(v3);
                    ah[mi][0] = __float_as_uint(h0); al[mi][0] = __float_as_uint(v0 - h0);
                    ah[mi][1] = __float_as_uint(h1); al[mi][1] = __float_as_uint(v1 - h1);
                    ah[mi][2] = __float_as_uint(h2); al[mi][2] = __float_as_uint(v2 - h2);
                    ah[mi][3] = __float_as_uint(h3); al[mi][3] = __float_as_uint(v3 - h3);
                } else {
                    ah[mi][0] = __float_as_uint(v0);
                    ah[mi][1] = __float_as_uint(v1);
                    ah[mi][2] = __float_as_uint(v2);
                    ah[mi][3] = __float_as_uint(v3);
                }
            }
#pragma unroll
            for (int nj = 0; nj < 8; nj++) {
                int n = wn * 64 + nj * 8 + g;
                float bv0 = Bs[bf][k8 + tg][n];
                float bv1 = Bs[bf][k8 + tg + 4][n];
                if (THREE) {
                    float bh0f = tf32r(bv0), bh1f = tf32r(bv1);
                    uint32_t bh0 = __float_as_uint(bh0f);
                    uint32_t bh1 = __float_as_uint(bh1f);
                    uint32_t bl0 = __float_as_uint(bv0 - bh0f);
                    uint32_t bl1 = __float_as_uint(bv1 - bh1f);
#pragma unroll
                    for (int mi = 0; mi < 2; mi++) {
                        mma_tf32(acc[mi][nj][0], acc[mi][nj][1], acc[mi][nj][2], acc[mi][nj][3],
                                 ah[mi][0], ah[mi][1], ah[mi][2], ah[mi][3], bh0, bh1);
                        mma_tf32(acc[mi][nj][0], acc[mi][nj][1], acc[mi][nj][2], acc[mi][nj][3],
                                 ah[mi][0], ah[mi][1], ah[mi][2], ah[mi][3], bl0, bl1);
                        mma_tf32(acc[mi][nj][0], acc[mi][nj][1], acc[mi][nj][2], acc[mi][nj][3],
                                 al[mi][0], al[mi][1], al[mi][2], al[mi][3], bh0, bh1);
                    }
                } else {
                    uint32_t bh0 = __float_as_uint(bv0);
                    uint32_t bh1 = __float_as_uint(bv1);
#pragma unroll
                    for (int mi = 0; mi < 2; mi++)
                        mma_tf32(acc[mi][nj][0], acc[mi][nj][1], acc[mi][nj][2], acc[mi][nj][3],
                                 ah[mi][0], ah[mi][1], ah[mi][2], ah[mi][3], bh0, bh1);
                }
            }
        }
        __syncthreads();
    }

    // epilogue: thread (g,tg) holds rows (.. + g, + 8), cols (.. + 2tg, +1)
#pragma unroll
    for (int mi = 0; mi < 2; mi++) {
#pragma unroll
        for (int nj = 0; nj < 8; nj++) {
            int row = m0 + wm * 32 + mi * 16 + g;
            int col = n0 + wn * 64 + nj * 8 + 2 * tg;
            float b0 = bias[col], b1 = bias[col + 1];
            float2 v0 = {acc[mi][nj][0] + b0, acc[mi][nj][1] + b1};
            float2 v1 = {acc[mi][nj][2] + b0, acc[mi][nj][3] + b1};
            *(float2*)(C + (size_t)row * N + col) = v0;
            *(float2*)(C + (size_t)(row + 8) * N + col) = v1;
        }
    }
}

// ---------------------------------------------------------------------------
// Flash attention via tf32 mma.sync (m16n8k8).
// Block = (b, h, 128 queries): 8 warps x 16 queries; 64-key tiles, cp.async
// double-buffered, shared by all 8 warps. No online max; softmax in base 2.
// P fed raw to mma (hw tf32 truncation); l sums full-precision exp2 —
// the ~6e-5 truncation bias mostly cancels in the normalization.
// Output pre-reshaped: Z[b][h*128 + 2d + (q>>9)][q&511] = av[b,h,q,d]
// ---------------------------------------------------------------------------
__global__ __launch_bounds__(256, 2) void attn_kernel() {
    __shared__ __align__(16) float Ks[2][64][20];
    __shared__ __align__(16) float Vs[2][64][68];

    int tid = threadIdx.x;
    int b = blockIdx.z, h = blockIdx.y;
    int q0 = blockIdx.x * 128;
    int w = tid >> 5;
    int lane = tid & 31;
    int g = lane >> 2, tg = lane & 3;

    const float* kvbase = d_kvbuf + (size_t)b * SEQL * KVD + h * 80;

    // --- cp.async tile-load assignments (16B each) ---
    int kr = tid >> 2, kc = (tid & 3) * 4;                  // K: 1 chunk/thread (64x16)
    const float* kgp_ = kvbase + (size_t)kr * KVD + kc;
    uint32_t ksm[2] = { s2u(&Ks[0][kr][kc]), s2u(&Ks[1][kr][kc]) };
    const float* vgp_[4];                                   // V: 4 chunks/thread (64x64)
    uint32_t vsm[2][4];
#pragma unroll
    for (int j = 0; j < 4; j++) {
        int idx = tid + j * 256;
        int r = idx >> 4, c = (idx & 15) * 4;
        vgp_[j] = kvbase + (size_t)r * KVD + 16 + c;
        vsm[0][j] = s2u(&Vs[0][r][c]);
        vsm[1][j] = s2u(&Vs[1][r][c]);
    }

    const float SC = 0.25f * 1.44269504088896340736f;
    int qA = q0 + w * 16 + g;
    int qB = qA + 8;
    const float* qp0 = d_qbuf + (size_t)(b * QL + qA) * QD + h * KD;
    const float* qp1 = d_qbuf + (size_t)(b * QL + qB) * QD + h * KD;
    uint32_t qa[2][4];
#pragma unroll
    for (int f = 0; f < 2; f++) {
        qa[f][0] = f2tf32(qp0[f * 8 + tg] * SC);
        qa[f][1] = f2tf32(qp1[f * 8 + tg] * SC);
        qa[f][2] = f2tf32(qp0[f * 8 + tg + 4] * SC);
        qa[f][3] = f2tf32(qp1[f * 8 + tg + 4] * SC);
    }

    float acc[8][4];
#pragma unroll
    for (int i = 0; i < 8; i++)
#pragma unroll
        for (int j = 0; j < 4; j++) acc[i][j] = 0.0f;
    float l0 = 0.0f, l1 = 0.0f;

    // prefetch tile 0
    cpasync16(ksm[0], kgp_);
#pragma unroll
    for (int j = 0; j < 4; j++) cpasync16(vsm[0][j], vgp_[j]);
    CP_COMMIT();

    const int NT = SEQL / 64;   // 64 tiles
    for (int t = 0; t < NT; ++t) {
        if (t + 1 < NT) {
            size_t off = (size_t)(t + 1) * 64 * KVD;
            int nbf = (t + 1) & 1;
            cpasync16(ksm[nbf], kgp_ + off);
#pragma unroll
            for (int j = 0; j < 4; j++) cpasync16(vsm[nbf][j], vgp_[j] + off);
        }
        CP_COMMIT();
        CP_WAIT1();
        __syncthreads();

        const int bf = t & 1;
#pragma unroll
        for (int kg = 0; kg < 8; kg++) {
            const int krow = kg * 8;
            const float* krp = &Ks[bf][krow + g][0];
            uint32_t kb00 = __float_as_uint(krp[tg]);
            uint32_t kb01 = __float_as_uint(krp[tg + 4]);
            uint32_t kb10 = __float_as_uint(krp[tg + 8]);
            uint32_t kb11 = __float_as_uint(krp[tg + 12]);

            float c0 = 0.f, c1 = 0.f, c2 = 0.f, c3 = 0.f;
            mma_tf32(c0, c1, c2, c3, qa[0][0], qa[0][1], qa[0][2], qa[0][3], kb00, kb01);
            mma_tf32(c0, c1, c2, c3, qa[1][0], qa[1][1], qa[1][2], qa[1][3], kb10, kb11);

            float p0 = ex2(c0), p1 = ex2(c1), p2 = ex2(c2), p3 = ex2(c3);
            l0 += p0 + p1;
            l1 += p2 + p3;
            uint32_t u0 = __float_as_uint(p0);
            uint32_t u1 = __float_as_uint(p1);
            uint32_t u2 = __float_as_uint(p2);
            uint32_t u3 = __float_as_uint(p3);

            // P as A-fragment: (u0,u2,u1,u3) with V rows permuted [0,2,4,6,1,3,5,7]
            const float* vr0 = &Vs[bf][krow + 2 * tg][0];
            const float* vr1 = &Vs[bf][krow + 2 * tg + 1][0];
#pragma unroll
            for (int nt = 0; nt < 8; nt++) {
                uint32_t vb0 = __float_as_uint(vr0[8 * nt + g]);
                uint32_t vb1 = __float_as_uint(vr1[8 * nt + g]);
                mma_tf32(acc[nt][0], acc[nt][1], acc[nt][2], acc[nt][3],
                         u0, u2, u1, u3, vb0, vb1);
            }
        }
        __syncthreads();
    }

    l0 += __shfl_xor_sync(0xffffffffu, l0, 1);
    l0 += __shfl_xor_sync(0xffffffffu, l0, 2);
    l1 += __shfl_xor_sync(0xffffffffu, l1, 1);
    l1 += __shfl_xor_sync(0xffffffffu, l1, 2);
    float r0 = 1.0f / l0, r1 = 1.0f / l1;

    float* zb = d_zbuf + (size_t)b * QL * COUT;
    int colA = qA & 511, hiA = qA >> 9;
    int colB = qB & 511, hiB = qB >> 9;
#pragma unroll
    for (int nt = 0; nt < 8; nt++) {
#pragma unroll
        for (int e = 0; e < 2; e++) {
            int d = 8 * nt + 2 * tg + e;
            zb[(size_t)(h * 128 + 2 * d + hiA) * COUT + colA] = acc[nt][e] * r0;
            zb[(size_t)(h * 128 + 2 * d + hiB) * COUT + colB] = acc[nt][2 + e] * r1;
        }
    }
}

// ---------------------------------------------------------------------------
// Launch
// ---------------------------------------------------------------------------
extern "C" void kernel_launch(void* const* d_in, const int* in_sizes, int n_in,
                              void* d_out, int out_size) {
    const float* x    = (const float*)d_in[0];
    const float* Wkv  = (const float*)d_in[1];
    const float* bkv  = (const float*)d_in[2];
    const float* gkv  = (const float*)d_in[3];
    const float* bekv = (const float*)d_in[4];
    const float* mkv  = (const float*)d_in[5];
    const float* vkv  = (const float*)d_in[6];
    const float* Wq   = (const float*)d_in[7];
    const float* bq   = (const float*)d_in[8];
    const float* gq   = (const float*)d_in[9];
    const float* beq  = (const float*)d_in[10];
    const float* mq   = (const float*)d_in[11];
    const float* vq   = (const float*)d_in[12];
    const float* Wp   = (const float*)d_in[13];
    const float* bp   = (const float*)d_in[14];
    const float* gp   = (const float*)d_in[15];
    const float* bep  = (const float*)d_in[16];
    const float* mp   = (const float*)d_in[17];
    const float* vp   = (const float*)d_in[18];
    float* out = (float*)d_out;

    fold_kernel<0><<<(CIN * KVD + 255) / 256, 256>>>(Wkv, bkv, gkv, bekv, mkv, vkv, CIN, KVD);
    fold_kernel<1><<<(CIN * QD + 255) / 256, 256>>>(Wq, bq, gq, beq, mq, vq, CIN, QD);
    fold_kernel<2><<<(COUT * COUT + 255) / 256, 256>>>(Wp, bp, gp, bep, mp, vp, COUT, COUT);

    // kv = BN(x @ Wkv + b):  [32768,256]x[256,640], tf32 (raw/truncate)
    tgemm_kernel<0, 0><<<dim3(KVD / 128, (BB * SEQL) / 128), 256>>>(x, nullptr, BB * SEQL, KVD, CIN);
    // q  = BN(xq @ Wq + b):  [8192,256]x[256,128], tf32 (strided gather)
    tgemm_kernel<1, 0><<<dim3(QD / 128, (BB * QL) / 128), 256>>>(x, nullptr, BB * QL, QD, CIN);
    // fused flash attention (tf32 mma) -> d_zbuf (TF-reshaped)
    attn_kernel<<<dim3(QL / 128, HH, BB), 256>>>();
    // out = BN(hardswish(Z) @ Wp + b): [8192,512]x[512,512], 3xTF32
    tgemm_kernel<2, 1><<<dim3(COUT / 128, (BB * QL) / 128), 256>>>(nullptr, out, BB * QL, COUT, COUT);
}

// round 11
// speedup vs baseline: 1.5142x; 1.5142x over previous
#include <cuda_runtime.h>
#include <math.h>
#include <stdint.h>

// Problem constants
#define BB   8
#define SEQL 4096
#define QL   1024
#define CIN  256
#define KVD  640
#define QD   128
#define HH   8
#define KD   16
#define VD   64
#define COUT 512
#define EPSB 1e-3f

typedef unsigned long long ull;

// Intermediates as __device__ globals (no dynamic allocation allowed)
__device__ float d_kvbuf[BB * SEQL * KVD];   // [B, SEQ, 640]  (BN folded)
__device__ float d_qbuf [BB * QL * QD];      // [B, QLEN, 128] (BN folded)
__device__ float d_zbuf [BB * QL * COUT];    // [B, 1024, 512] attention out, TF-reshaped
__device__ float d_Wkvf[CIN * KVD];
__device__ float d_bkvf[KVD];
__device__ float d_Wqf [CIN * QD];
__device__ float d_bqf [QD];
__device__ float d_Wpf [COUT * COUT];
__device__ float d_bpf [COUT];

__device__ __forceinline__ float ex2(float x) {
    float y;
    asm("ex2.approx.ftz.f32 %0, %1;" : "=f"(y) : "f"(x));
    return y;
}
__device__ __forceinline__ uint32_t s2u(const void* p) {
    return (uint32_t)__cvta_generic_to_shared(p);
}
__device__ __forceinline__ void cpasync16(uint32_t dst, const void* src) {
    asm volatile("cp.async.cg.shared.global [%0], [%1], 16;" :: "r"(dst), "l"(src));
}
#define CP_COMMIT() asm volatile("cp.async.commit_group;")
#define CP_WAIT1()  asm volatile("cp.async.wait_group 1;")

// tf32 round-to-nearest conversion (f32 bit pattern, low 13 bits zero)
__device__ __forceinline__ uint32_t f2tf32(float x) {
    uint32_t r;
    asm("cvt.rna.tf32.f32 %0, %1;" : "=r"(r) : "f"(x));
    return r;
}
__device__ __forceinline__ float tf32r(float x) {
    return __uint_as_float(f2tf32(x));
}
// m16n8k8 tf32 MMA, D = A*B + D
__device__ __forceinline__ void mma_tf32(float& c0, float& c1, float& c2, float& c3,
                                         uint32_t a0, uint32_t a1, uint32_t a2, uint32_t a3,
                                         uint32_t b0, uint32_t b1) {
    asm volatile("mma.sync.aligned.m16n8k8.row.col.f32.tf32.tf32.f32 "
                 "{%0,%1,%2,%3}, {%4,%5,%6,%7}, {%8,%9}, {%0,%1,%2,%3};"
                 : "+f"(c0), "+f"(c1), "+f"(c2), "+f"(c3)
                 : "r"(a0), "r"(a1), "r"(a2), "r"(a3), "r"(b0), "r"(b1));
}

__device__ __forceinline__ float hswish(float x) {
    return x * __saturatef(x * (1.0f / 6.0f) + 0.5f);
}

// ---------------------------------------------------------------------------
// Fold BN into weights + bias.
// ---------------------------------------------------------------------------
template <int WHICH>
__global__ void fold_kernel(const float* __restrict__ W, const float* __restrict__ b,
                            const float* __restrict__ gam, const float* __restrict__ bet,
                            const float* __restrict__ mu, const float* __restrict__ var,
                            int K, int N) {
    float* Wf; float* bf;
    if (WHICH == 0)      { Wf = d_Wkvf; bf = d_bkvf; }
    else if (WHICH == 1) { Wf = d_Wqf;  bf = d_bqf;  }
    else                 { Wf = d_Wpf;  bf = d_bpf;  }
    int i = blockIdx.x * 256 + threadIdx.x;
    if (i < K * N) {
        int n = i % N;
        float s = gam[n] * rsqrtf(var[n] + EPSB);
        Wf[i] = W[i] * s;
    }
    if (i < N) {
        float s = gam[i] * rsqrtf(var[i] + EPSB);
        bf[i] = (b[i] - mu[i]) * s + bet[i];
    }
}

// ---------------------------------------------------------------------------
// tf32 tensor-core GEMM with register-prefetch pipelining:
// C[M,N] = f(A[M,K]) @ W[K,N] + bias
// BM=128, BN=128, BK=16, 256 threads (8 warps as 4m x 2n, warp tile 32x64).
// A and W rounded to tf32 (rna) on smem store; both stored [k][*] (132-padded)
// so all fragment LDS are conflict-free. Tile t+1's global loads are issued
// into registers before tile t's mma loop, hiding global latency.
// THREE=1: 3xTF32 (hi/lo split, hi*hi + hi*lo + lo*hi) for fp32-grade accuracy.
// MODE 0: kv (A=x), 1: q (A=x strided gather), 2: proj (A=hswish(zbuf)).
// ---------------------------------------------------------------------------
template <int MODE, int THREE>
__global__ __launch_bounds__(256) void tgemm_kernel(const float* __restrict__ Ain,
                                                    float* __restrict__ Cout,
                                                    int M, int N, int K) {
    const float* W;  const float* bias;  float* C;  const float* A = Ain;
    if (MODE == 0)      { W = d_Wkvf; bias = d_bkvf; C = d_kvbuf; }
    else if (MODE == 1) { W = d_Wqf;  bias = d_bqf;  C = d_qbuf;  }
    else                { W = d_Wpf;  bias = d_bpf;  C = Cout; A = d_zbuf; }

    __shared__ __align__(16) float Ah[16][132];
    __shared__ __align__(16) float Bh[16][132];
    __shared__ __align__(16) float Al[THREE ? 16 : 1][THREE ? 132 : 4];
    __shared__ __align__(16) float Bl[THREE ? 16 : 1][THREE ? 132 : 4];

    int tid  = threadIdx.x;
    int m0 = blockIdx.y * 128;
    int n0 = blockIdx.x * 128;
    int w = tid >> 5, lane = tid & 31;
    int g = lane >> 2, tg = lane & 3;
    int wm = w >> 1, wn = w & 1;           // warp tile: rows wm*32+, cols wn*64+

    float acc[2][8][4];
#pragma unroll
    for (int i = 0; i < 2; i++)
#pragma unroll
        for (int j = 0; j < 8; j++)
#pragma unroll
            for (int e = 0; e < 4; e++) acc[i][j][e] = 0.0f;

    // A-load assignment: 2 float4 per thread (128 rows x 16 cols)
    int lrow[2], lc4[2];
    const float* aptr[2];
#pragma unroll
    for (int j = 0; j < 2; j++) {
        int idx = tid + j * 256;
        int r = idx >> 2, c4 = idx & 3;
        lrow[j] = r; lc4[j] = c4;
        int gr = m0 + r;
        int src;
        if (MODE == 1) {
            int bb = gr >> 10, ql = gr & 1023;
            int qy = ql >> 5, qx = ql & 31;
            src = (bb << 12) + (qy << 7) + (qx << 1);
        } else {
            src = gr;
        }
        aptr[j] = A + (size_t)src * K + c4 * 4;
    }
    // B-load: 2 float4 per thread (16 rows x 128 cols)
    int bkr[2], bnc[2];
    const float* bptr[2];
#pragma unroll
    for (int j = 0; j < 2; j++) {
        int idx = tid + j * 256;
        bkr[j] = idx >> 5; bnc[j] = (idx & 31) * 4;
        bptr[j] = W + (size_t)bkr[j] * N + n0 + bnc[j];
    }

    // prefetch tile 0 into registers
    float4 aReg[2], bReg[2];
#pragma unroll
    for (int j = 0; j < 2; j++) {
        aReg[j] = *(const float4*)(aptr[j]);
        bReg[j] = *(const float4*)(bptr[j]);
    }

    const int NT = K / 16;
    for (int t = 0; t < NT; ++t) {
        // --- stage tile t from registers into smem (tf32-rounded, +lo) ---
#pragma unroll
        for (int j = 0; j < 2; j++) {
            float4 a = aReg[j];
            if (MODE == 2) { a.x = hswish(a.x); a.y = hswish(a.y); a.z = hswish(a.z); a.w = hswish(a.w); }
            float av[4] = {a.x, a.y, a.z, a.w};
#pragma unroll
            for (int e = 0; e < 4; e++) {
                float h = tf32r(av[e]);
                Ah[lc4[j] * 4 + e][lrow[j]] = h;
                if (THREE) Al[lc4[j] * 4 + e][lrow[j]] = av[e] - h;
            }
            float4 b = bReg[j];
            float4 h4 = {tf32r(b.x), tf32r(b.y), tf32r(b.z), tf32r(b.w)};
            *(float4*)&Bh[bkr[j]][bnc[j]] = h4;
            if (THREE) {
                float4 lo = {b.x - h4.x, b.y - h4.y, b.z - h4.z, b.w - h4.w};
                *(float4*)&Bl[bkr[j]][bnc[j]] = lo;
            }
        }
        __syncthreads();

        // --- issue tile t+1 global loads (latency hidden behind mma loop) ---
        if (t + 1 < NT) {
            int k0 = (t + 1) * 16;
#pragma unroll
            for (int j = 0; j < 2; j++) {
                aReg[j] = *(const float4*)(aptr[j] + k0);
                bReg[j] = *(const float4*)(bptr[j] + (size_t)k0 * N);
            }
        }

        // --- compute tile t ---
#pragma unroll
        for (int k8 = 0; k8 < 16; k8 += 8) {
            uint32_t ah[2][4], al[2][4];
#pragma unroll
            for (int mi = 0; mi < 2; mi++) {
                int r = wm * 32 + mi * 16 + g;
                ah[mi][0] = __float_as_uint(Ah[k8 + tg][r]);
                ah[mi][1] = __float_as_uint(Ah[k8 + tg][r + 8]);
                ah[mi][2] = __float_as_uint(Ah[k8 + tg + 4][r]);
                ah[mi][3] = __float_as_uint(Ah[k8 + tg + 4][r + 8]);
                if (THREE) {
                    al[mi][0] = __float_as_uint(Al[k8 + tg][r]);
                    al[mi][1] = __float_as_uint(Al[k8 + tg][r + 8]);
                    al[mi][2] = __float_as_uint(Al[k8 + tg + 4][r]);
                    al[mi][3] = __float_as_uint(Al[k8 + tg + 4][r + 8]);
                }
            }
#pragma unroll
            for (int nj = 0; nj < 8; nj++) {
                int n = wn * 64 + nj * 8 + g;
                uint32_t bh0 = __float_as_uint(Bh[k8 + tg][n]);
                uint32_t bh1 = __float_as_uint(Bh[k8 + tg + 4][n]);
#pragma unroll
                for (int mi = 0; mi < 2; mi++)
                    mma_tf32(acc[mi][nj][0], acc[mi][nj][1], acc[mi][nj][2], acc[mi][nj][3],
                             ah[mi][0], ah[mi][1], ah[mi][2], ah[mi][3], bh0, bh1);
                if (THREE) {
                    uint32_t bl0 = __float_as_uint(Bl[k8 + tg][n]);
                    uint32_t bl1 = __float_as_uint(Bl[k8 + tg + 4][n]);
#pragma unroll
                    for (int mi = 0; mi < 2; mi++) {
                        mma_tf32(acc[mi][nj][0], acc[mi][nj][1], acc[mi][nj][2], acc[mi][nj][3],
                                 ah[mi][0], ah[mi][1], ah[mi][2], ah[mi][3], bl0, bl1);
                        mma_tf32(acc[mi][nj][0], acc[mi][nj][1], acc[mi][nj][2], acc[mi][nj][3],
                                 al[mi][0], al[mi][1], al[mi][2], al[mi][3], bh0, bh1);
                    }
                }
            }
        }
        __syncthreads();
    }

    // epilogue: thread (g,tg) holds rows (.. + g, + 8), cols (.. + 2tg, +1)
#pragma unroll
    for (int mi = 0; mi < 2; mi++) {
#pragma unroll
        for (int nj = 0; nj < 8; nj++) {
            int row = m0 + wm * 32 + mi * 16 + g;
            int col = n0 + wn * 64 + nj * 8 + 2 * tg;
            float b0 = bias[col], b1 = bias[col + 1];
            float2 v0 = {acc[mi][nj][0] + b0, acc[mi][nj][1] + b1};
            float2 v1 = {acc[mi][nj][2] + b0, acc[mi][nj][3] + b1};
            *(float2*)(C + (size_t)row * N + col) = v0;
            *(float2*)(C + (size_t)(row + 8) * N + col) = v1;
        }
    }
}

// ---------------------------------------------------------------------------
// Flash attention via tf32 mma.sync (m16n8k8) — the proven R6/R8 version.
// Block = (b, h, 64 queries): 4 warps x 16 queries. 32-key tiles, cp.async
// double-buffered. No online max; softmax in base 2; P tf32-masked so the
// l-sum matches the mma operand exactly.
// Output pre-reshaped: Z[b][h*128 + 2d + (q>>9)][q&511] = av[b,h,q,d]
// ---------------------------------------------------------------------------
__global__ __launch_bounds__(128) void attn_kernel() {
    __shared__ __align__(16) float Ks[2][32][20];
    __shared__ __align__(16) float Vs[2][32][68];

    int tid = threadIdx.x;
    int b = blockIdx.z, h = blockIdx.y;
    int q0 = blockIdx.x * 64;
    int w = tid >> 5;
    int lane = tid & 31;
    int g = lane >> 2, tg = lane & 3;

    const float* kvbase = d_kvbuf + (size_t)b * SEQL * KVD + h * 80;

    int kr = tid >> 2, kc = (tid & 3) * 4;
    const float* kgp_ = kvbase + (size_t)kr * KVD + kc;
    uint32_t ksm[2] = { s2u(&Ks[0][kr][kc]), s2u(&Ks[1][kr][kc]) };
    const float* vgp_[4];
    uint32_t vsm[2][4];
#pragma unroll
    for (int j = 0; j < 4; j++) {
        int idx = tid + j * 128;
        int r = idx >> 4, c = (idx & 15) * 4;
        vgp_[j] = kvbase + (size_t)r * KVD + 16 + c;
        vsm[0][j] = s2u(&Vs[0][r][c]);
        vsm[1][j] = s2u(&Vs[1][r][c]);
    }

    const float SC = 0.25f * 1.44269504088896340736f;
    int qA = q0 + w * 16 + g;
    int qB = qA + 8;
    const float* qp0 = d_qbuf + (size_t)(b * QL + qA) * QD + h * KD;
    const float* qp1 = d_qbuf + (size_t)(b * QL + qB) * QD + h * KD;
    uint32_t qa[2][4];
#pragma unroll
    for (int f = 0; f < 2; f++) {
        qa[f][0] = f2tf32(qp0[f * 8 + tg] * SC);
        qa[f][1] = f2tf32(qp1[f * 8 + tg] * SC);
        qa[f][2] = f2tf32(qp0[f * 8 + tg + 4] * SC);
        qa[f][3] = f2tf32(qp1[f * 8 + tg + 4] * SC);
    }

    float acc[8][4];
#pragma unroll
    for (int i = 0; i < 8; i++)
#pragma unroll
        for (int j = 0; j < 4; j++) acc[i][j] = 0.0f;
    float l0 = 0.0f, l1 = 0.0f;

    cpasync16(ksm[0], kgp_);
#pragma unroll
    for (int j = 0; j < 4; j++) cpasync16(vsm[0][j], vgp_[j]);
    CP_COMMIT();

    const int NT = SEQL / 32;
    for (int t = 0; t < NT; ++t) {
        if (t + 1 < NT) {
            size_t off = (size_t)(t + 1) * 32 * KVD;
            int nbf = (t + 1) & 1;
            cpasync16(ksm[nbf], kgp_ + off);
#pragma unroll
            for (int j = 0; j < 4; j++) cpasync16(vsm[nbf][j], vgp_[j] + off);
        }
        CP_COMMIT();
        CP_WAIT1();
        __syncthreads();

        const int bf = t & 1;
#pragma unroll
        for (int kg = 0; kg < 4; kg++) {
            const int krow = kg * 8;
            const float* krp = &Ks[bf][krow + g][0];
            uint32_t kb00 = __float_as_uint(krp[tg]);
            uint32_t kb01 = __float_as_uint(krp[tg + 4]);
            uint32_t kb10 = __float_as_uint(krp[tg + 8]);
            uint32_t kb11 = __float_as_uint(krp[tg + 12]);

            float c0 = 0.f, c1 = 0.f, c2 = 0.f, c3 = 0.f;
            mma_tf32(c0, c1, c2, c3, qa[0][0], qa[0][1], qa[0][2], qa[0][3], kb00, kb01);
            mma_tf32(c0, c1, c2, c3, qa[1][0], qa[1][1], qa[1][2], qa[1][3], kb10, kb11);

            uint32_t u0 = __float_as_uint(ex2(c0)) & 0xFFFFE000u;
            uint32_t u1 = __float_as_uint(ex2(c1)) & 0xFFFFE000u;
            uint32_t u2 = __float_as_uint(ex2(c2)) & 0xFFFFE000u;
            uint32_t u3 = __float_as_uint(ex2(c3)) & 0xFFFFE000u;
            l0 += __uint_as_float(u0) + __uint_as_float(u1);
            l1 += __uint_as_float(u2) + __uint_as_float(u3);

            const float* vr0 = &Vs[bf][krow + 2 * tg][0];
            const float* vr1 = &Vs[bf][krow + 2 * tg + 1][0];
#pragma unroll
            for (int nt = 0; nt < 8; nt++) {
                uint32_t vb0 = __float_as_uint(vr0[8 * nt + g]);
                uint32_t vb1 = __float_as_uint(vr1[8 * nt + g]);
                mma_tf32(acc[nt][0], acc[nt][1], acc[nt][2], acc[nt][3],
                         u0, u2, u1, u3, vb0, vb1);
            }
        }
        __syncthreads();
    }

    l0 += __shfl_xor_sync(0xffffffffu, l0, 1);
    l0 += __shfl_xor_sync(0xffffffffu, l0, 2);
    l1 += __shfl_xor_sync(0xffffffffu, l1, 1);
    l1 += __shfl_xor_sync(0xffffffffu, l1, 2);
    float r0 = 1.0f / l0, r1 = 1.0f / l1;

    float* zb = d_zbuf + (size_t)b * QL * COUT;
    int colA = qA & 511, hiA = qA >> 9;
    int colB = qB & 511, hiB = qB >> 9;
#pragma unroll
    for (int nt = 0; nt < 8; nt++) {
#pragma unroll
        for (int e = 0; e < 2; e++) {
            int d = 8 * nt + 2 * tg + e;
            zb[(size_t)(h * 128 + 2 * d + hiA) * COUT + colA] = acc[nt][e] * r0;
            zb[(size_t)(h * 128 + 2 * d + hiB) * COUT + colB] = acc[nt][2 + e] * r1;
        }
    }
}

// ---------------------------------------------------------------------------
// Launch
// ---------------------------------------------------------------------------
extern "C" void kernel_launch(void* const* d_in, const int* in_sizes, int n_in,
                              void* d_out, int out_size) {
    const float* x    = (const float*)d_in[0];
    const float* Wkv  = (const float*)d_in[1];
    const float* bkv  = (const float*)d_in[2];
    const float* gkv  = (const float*)d_in[3];
    const float* bekv = (const float*)d_in[4];
    const float* mkv  = (const float*)d_in[5];
    const float* vkv  = (const float*)d_in[6];
    const float* Wq   = (const float*)d_in[7];
    const float* bq   = (const float*)d_in[8];
    const float* gq   = (const float*)d_in[9];
    const float* beq  = (const float*)d_in[10];
    const float* mq   = (const float*)d_in[11];
    const float* vq   = (const float*)d_in[12];
    const float* Wp   = (const float*)d_in[13];
    const float* bp   = (const float*)d_in[14];
    const float* gp   = (const float*)d_in[15];
    const float* bep  = (const float*)d_in[16];
    const float* mp   = (const float*)d_in[17];
    const float* vp   = (const float*)d_in[18];
    float* out = (float*)d_out;

    fold_kernel<0><<<(CIN * KVD + 255) / 256, 256>>>(Wkv, bkv, gkv, bekv, mkv, vkv, CIN, KVD);
    fold_kernel<1><<<(CIN * QD + 255) / 256, 256>>>(Wq, bq, gq, beq, mq, vq, CIN, QD);
    fold_kernel<2><<<(COUT * COUT + 255) / 256, 256>>>(Wp, bp, gp, bep, mp, vp, COUT, COUT);

    // kv = BN(x @ Wkv + b):  [32768,256]x[256,640], tf32 (rna-rounded)
    tgemm_kernel<0, 0><<<dim3(KVD / 128, (BB * SEQL) / 128), 256>>>(x, nullptr, BB * SEQL, KVD, CIN);
    // q  = BN(xq @ Wq + b):  [8192,256]x[256,128], tf32 (strided gather)
    tgemm_kernel<1, 0><<<dim3(QD / 128, (BB * QL) / 128), 256>>>(x, nullptr, BB * QL, QD, CIN);
    // fused flash attention (tf32 mma) -> d_zbuf (TF-reshaped)
    attn_kernel<<<dim3(QL / 64, HH, BB), 128>>>();
    // out = BN(hardswish(Z) @ Wp + b): [8192,512]x[512,512], 3xTF32
    tgemm_kernel<2, 1><<<dim3(COUT / 128, (BB * QL) / 128), 256>>>(nullptr, out, BB * QL, COUT, COUT);
}

// round 12
// speedup vs baseline: 1.9220x; 1.2693x over previous
#include <cuda_runtime.h>
#include <cuda_bf16.h>
#include <math.h>
#include <stdint.h>

// Problem constants
#define BB   8
#define SEQL 4096
#define QL   1024
#define CIN  256
#define KVD  640
#define QD   128
#define HH   8
#define KD   16
#define VD   64
#define COUT 512
#define EPSB 1e-3f

// Intermediates as __device__ globals (no dynamic allocation allowed)
__device__ __nv_bfloat16 d_Kb[BB * HH * SEQL * KD];   // K bf16 [b][h][seq][16]
__device__ __nv_bfloat16 d_Vt[BB * HH * VD * SEQL];   // V bf16 transposed [b][h][dim][seq]
__device__ float d_qbuf [BB * QL * QD];               // [B, QLEN, 128] (BN folded)
__device__ float d_zbuf [BB * QL * COUT];              // attention out, TF-reshaped
__device__ float d_Wkvf[CIN * KVD];
__device__ float d_bkvf[KVD];
__device__ float d_Wqf [CIN * QD];
__device__ float d_bqf [QD];
__device__ float d_Wpf [COUT * COUT];
__device__ float d_bpf [COUT];

__device__ __forceinline__ float ex2(float x) {
    float y;
    asm("ex2.approx.ftz.f32 %0, %1;" : "=f"(y) : "f"(x));
    return y;
}
__device__ __forceinline__ uint32_t s2u(const void* p) {
    return (uint32_t)__cvta_generic_to_shared(p);
}
__device__ __forceinline__ void cpasync16(uint32_t dst, const void* src) {
    asm volatile("cp.async.cg.shared.global [%0], [%1], 16;" :: "r"(dst), "l"(src));
}
#define CP_COMMIT() asm volatile("cp.async.commit_group;")
#define CP_WAIT1()  asm volatile("cp.async.wait_group 1;")

// tf32 round-to-nearest conversion
__device__ __forceinline__ uint32_t f2tf32(float x) {
    uint32_t r;
    asm("cvt.rna.tf32.f32 %0, %1;" : "=r"(r) : "f"(x));
    return r;
}
__device__ __forceinline__ float tf32r(float x) {
    return __uint_as_float(f2tf32(x));
}
// m16n8k8 tf32 MMA, D = A*B + D
__device__ __forceinline__ void mma_tf32(float& c0, float& c1, float& c2, float& c3,
                                         uint32_t a0, uint32_t a1, uint32_t a2, uint32_t a3,
                                         uint32_t b0, uint32_t b1) {
    asm volatile("mma.sync.aligned.m16n8k8.row.col.f32.tf32.tf32.f32 "
                 "{%0,%1,%2,%3}, {%4,%5,%6,%7}, {%8,%9}, {%0,%1,%2,%3};"
                 : "+f"(c0), "+f"(c1), "+f"(c2), "+f"(c3)
                 : "r"(a0), "r"(a1), "r"(a2), "r"(a3), "r"(b0), "r"(b1));
}
// m16n8k16 bf16 MMA, D = A*B + D
__device__ __forceinline__ void mma_bf16(float& c0, float& c1, float& c2, float& c3,
                                         uint32_t a0, uint32_t a1, uint32_t a2, uint32_t a3,
                                         uint32_t b0, uint32_t b1) {
    asm volatile("mma.sync.aligned.m16n8k16.row.col.f32.bf16.bf16.f32 "
                 "{%0,%1,%2,%3}, {%4,%5,%6,%7}, {%8,%9}, {%0,%1,%2,%3};"
                 : "+f"(c0), "+f"(c1), "+f"(c2), "+f"(c3)
                 : "r"(a0), "r"(a1), "r"(a2), "r"(a3), "r"(b0), "r"(b1));
}
// pack two fp32 into bf16x2 (lo = first arg in low 16 bits)
__device__ __forceinline__ uint32_t packbf(float lo, float hi) {
    __nv_bfloat162 p = __floats2bfloat162_rn(lo, hi);
    return *(uint32_t*)&p;
}

__device__ __forceinline__ float hswish(float x) {
    return x * __saturatef(x * (1.0f / 6.0f) + 0.5f);
}

// ---------------------------------------------------------------------------
// Fold BN into weights + bias.
// ---------------------------------------------------------------------------
template <int WHICH>
__global__ void fold_kernel(const float* __restrict__ W, const float* __restrict__ b,
                            const float* __restrict__ gam, const float* __restrict__ bet,
                            const float* __restrict__ mu, const float* __restrict__ var,
                            int K, int N) {
    float* Wf; float* bf;
    if (WHICH == 0)      { Wf = d_Wkvf; bf = d_bkvf; }
    else if (WHICH == 1) { Wf = d_Wqf;  bf = d_bqf;  }
    else                 { Wf = d_Wpf;  bf = d_bpf;  }
    int i = blockIdx.x * 256 + threadIdx.x;
    if (i < K * N) {
        int n = i % N;
        float s = gam[n] * rsqrtf(var[n] + EPSB);
        Wf[i] = W[i] * s;
    }
    if (i < N) {
        float s = gam[i] * rsqrtf(var[i] + EPSB);
        bf[i] = (b[i] - mu[i]) * s + bet[i];
    }
}

// ---------------------------------------------------------------------------
// tf32 tensor-core GEMM with register-prefetch pipelining (R11 structure).
// MODE 0: kv (A=x) -> custom epilogue: K rows to d_Kb (bf16), V transposed
//         to d_Vt (bf16). No fp32 kv buffer at all.
// MODE 1: q (A=x strided gather) -> d_qbuf fp32.
// MODE 2: proj (A=hswish(zbuf)), THREE=1 (3xTF32) -> d_out fp32.
// ---------------------------------------------------------------------------
template <int MODE, int THREE>
__global__ __launch_bounds__(256) void tgemm_kernel(const float* __restrict__ Ain,
                                                    float* __restrict__ Cout,
                                                    int M, int N, int K) {
    const float* W;  const float* bias;  float* C;  const float* A = Ain;
    if (MODE == 0)      { W = d_Wkvf; bias = d_bkvf; C = nullptr;  }
    else if (MODE == 1) { W = d_Wqf;  bias = d_bqf;  C = d_qbuf;   }
    else                { W = d_Wpf;  bias = d_bpf;  C = Cout; A = d_zbuf; }

    __shared__ __align__(16) float Ah[16][132];
    __shared__ __align__(16) float Bh[16][132];
    __shared__ __align__(16) float Al[THREE ? 16 : 1][THREE ? 132 : 4];
    __shared__ __align__(16) float Bl[THREE ? 16 : 1][THREE ? 132 : 4];

    int tid  = threadIdx.x;
    int m0 = blockIdx.y * 128;
    int n0 = blockIdx.x * 128;
    int w = tid >> 5, lane = tid & 31;
    int g = lane >> 2, tg = lane & 3;
    int wm = w >> 1, wn = w & 1;

    float acc[2][8][4];
#pragma unroll
    for (int i = 0; i < 2; i++)
#pragma unroll
        for (int j = 0; j < 8; j++)
#pragma unroll
            for (int e = 0; e < 4; e++) acc[i][j][e] = 0.0f;

    int lrow[2], lc4[2];
    const float* aptr[2];
#pragma unroll
    for (int j = 0; j < 2; j++) {
        int idx = tid + j * 256;
        int r = idx >> 2, c4 = idx & 3;
        lrow[j] = r; lc4[j] = c4;
        int gr = m0 + r;
        int src;
        if (MODE == 1) {
            int bb = gr >> 10, ql = gr & 1023;
            int qy = ql >> 5, qx = ql & 31;
            src = (bb << 12) + (qy << 7) + (qx << 1);
        } else {
            src = gr;
        }
        aptr[j] = A + (size_t)src * K + c4 * 4;
    }
    int bkr[2], bnc[2];
    const float* bptr[2];
#pragma unroll
    for (int j = 0; j < 2; j++) {
        int idx = tid + j * 256;
        bkr[j] = idx >> 5; bnc[j] = (idx & 31) * 4;
        bptr[j] = W + (size_t)bkr[j] * N + n0 + bnc[j];
    }

    float4 aReg[2], bReg[2];
#pragma unroll
    for (int j = 0; j < 2; j++) {
        aReg[j] = *(const float4*)(aptr[j]);
        bReg[j] = *(const float4*)(bptr[j]);
    }

    const int NT = K / 16;
    for (int t = 0; t < NT; ++t) {
#pragma unroll
        for (int j = 0; j < 2; j++) {
            float4 a = aReg[j];
            if (MODE == 2) { a.x = hswish(a.x); a.y = hswish(a.y); a.z = hswish(a.z); a.w = hswish(a.w); }
            float av[4] = {a.x, a.y, a.z, a.w};
#pragma unroll
            for (int e = 0; e < 4; e++) {
                float h = tf32r(av[e]);
                Ah[lc4[j] * 4 + e][lrow[j]] = h;
                if (THREE) Al[lc4[j] * 4 + e][lrow[j]] = av[e] - h;
            }
            float4 b = bReg[j];
            float4 h4 = {tf32r(b.x), tf32r(b.y), tf32r(b.z), tf32r(b.w)};
            *(float4*)&Bh[bkr[j]][bnc[j]] = h4;
            if (THREE) {
                float4 lo = {b.x - h4.x, b.y - h4.y, b.z - h4.z, b.w - h4.w};
                *(float4*)&Bl[bkr[j]][bnc[j]] = lo;
            }
        }
        __syncthreads();

        if (t + 1 < NT) {
            int k0 = (t + 1) * 16;
#pragma unroll
            for (int j = 0; j < 2; j++) {
                aReg[j] = *(const float4*)(aptr[j] + k0);
                bReg[j] = *(const float4*)(bptr[j] + (size_t)k0 * N);
            }
        }

#pragma unroll
        for (int k8 = 0; k8 < 16; k8 += 8) {
            uint32_t ah[2][4], al[2][4];
#pragma unroll
            for (int mi = 0; mi < 2; mi++) {
                int r = wm * 32 + mi * 16 + g;
                ah[mi][0] = __float_as_uint(Ah[k8 + tg][r]);
                ah[mi][1] = __float_as_uint(Ah[k8 + tg][r + 8]);
                ah[mi][2] = __float_as_uint(Ah[k8 + tg + 4][r]);
                ah[mi][3] = __float_as_uint(Ah[k8 + tg + 4][r + 8]);
                if (THREE) {
                    al[mi][0] = __float_as_uint(Al[k8 + tg][r]);
                    al[mi][1] = __float_as_uint(Al[k8 + tg][r + 8]);
                    al[mi][2] = __float_as_uint(Al[k8 + tg + 4][r]);
                    al[mi][3] = __float_as_uint(Al[k8 + tg + 4][r + 8]);
                }
            }
#pragma unroll
            for (int nj = 0; nj < 8; nj++) {
                int n = wn * 64 + nj * 8 + g;
                uint32_t bh0 = __float_as_uint(Bh[k8 + tg][n]);
                uint32_t bh1 = __float_as_uint(Bh[k8 + tg + 4][n]);
#pragma unroll
                for (int mi = 0; mi < 2; mi++)
                    mma_tf32(acc[mi][nj][0], acc[mi][nj][1], acc[mi][nj][2], acc[mi][nj][3],
                             ah[mi][0], ah[mi][1], ah[mi][2], ah[mi][3], bh0, bh1);
                if (THREE) {
                    uint32_t bl0 = __float_as_uint(Bl[k8 + tg][n]);
                    uint32_t bl1 = __float_as_uint(Bl[k8 + tg + 4][n]);
#pragma unroll
                    for (int mi = 0; mi < 2; mi++) {
                        mma_tf32(acc[mi][nj][0], acc[mi][nj][1], acc[mi][nj][2], acc[mi][nj][3],
                                 ah[mi][0], ah[mi][1], ah[mi][2], ah[mi][3], bl0, bl1);
                        mma_tf32(acc[mi][nj][0], acc[mi][nj][1], acc[mi][nj][2], acc[mi][nj][3],
                                 al[mi][0], al[mi][1], al[mi][2], al[mi][3], bh0, bh1);
                    }
                }
            }
        }
        __syncthreads();
    }

    // epilogue: thread (g,tg) holds rows (.. + g, + 8), cols (.. + 2tg, +1)
#pragma unroll
    for (int mi = 0; mi < 2; mi++) {
#pragma unroll
        for (int nj = 0; nj < 8; nj++) {
            int row = m0 + wm * 32 + mi * 16 + g;
            int col = n0 + wn * 64 + nj * 8 + 2 * tg;
            float b0 = bias[col], b1 = bias[col + 1];
            float v00 = acc[mi][nj][0] + b0, v01 = acc[mi][nj][1] + b1;  // row
            float v10 = acc[mi][nj][2] + b0, v11 = acc[mi][nj][3] + b1;  // row+8
            if (MODE == 0) {
                // scatter to K (bf16 pairs) / V-transposed (bf16 scalars)
                int bb = row >> 12, seq = row & 4095;
                int hh = col / 80, c = col - hh * 80;   // col even -> pair stays in region
                if (c < KD) {
                    __nv_bfloat162 p0 = __floats2bfloat162_rn(v00, v01);
                    __nv_bfloat162 p1 = __floats2bfloat162_rn(v10, v11);
                    size_t kbase = ((size_t)(bb * HH + hh) * SEQL + seq) * KD + c;
                    *(__nv_bfloat162*)&d_Kb[kbase] = p0;
                    *(__nv_bfloat162*)&d_Kb[kbase + 8 * KD] = p1;
                } else {
                    int dd = c - KD;
                    size_t vbase = ((size_t)(bb * HH + hh) * VD + dd) * SEQL + seq;
                    d_Vt[vbase]            = __float2bfloat16_rn(v00);
                    d_Vt[vbase + SEQL]     = __float2bfloat16_rn(v01);
                    d_Vt[vbase + 8]        = __float2bfloat16_rn(v10);
                    d_Vt[vbase + SEQL + 8] = __float2bfloat16_rn(v11);
                }
            } else {
                float2 o0 = {v00, v01};
                float2 o1 = {v10, v11};
                *(float2*)(C + (size_t)row * N + col) = o0;
                *(float2*)(C + (size_t)(row + 8) * N + col) = o1;
            }
        }
    }
}

// ---------------------------------------------------------------------------
// Flash attention via bf16 mma.sync (m16n8k16).
// Block = (b, h, 64 queries): 4 warps x 16 queries. 32-key tiles, cp.async
// double-buffered. No online max; softmax in base 2.
// K tile:  [32 keys][16 dims] bf16, row stride 24 elems (48B; banks 12g+tg).
// V tile:  [64 dims][32 keys] bf16 (pre-transposed in global), row stride 40
//          elems (80B; banks 20g+tg). Both conflict-free for LDS.32 frags.
// S accum packs directly into the AV A-fragment (natural key order).
// Output pre-reshaped: Z[b][h*128 + 2d + (q>>9)][q&511] = av[b,h,q,d]
// ---------------------------------------------------------------------------
__global__ __launch_bounds__(128) void attn_kernel() {
    __shared__ __align__(16) __nv_bfloat16 Ks[2][32][24];
    __shared__ __align__(16) __nv_bfloat16 Vs[2][64][40];

    int tid = threadIdx.x;
    int b = blockIdx.z, h = blockIdx.y;
    int q0 = blockIdx.x * 64;
    int w = tid >> 5;
    int lane = tid & 31;
    int g = lane >> 2, tg = lane & 3;

    const __nv_bfloat16* Kg = d_Kb + (size_t)(b * HH + h) * SEQL * KD;
    const __nv_bfloat16* Vg = d_Vt + (size_t)(b * HH + h) * VD * SEQL;

    // K tile: 32 rows x 32B = 64 chunks of 16B; threads 0..63
    const __nv_bfloat16* kgp = nullptr;
    uint32_t ksm[2] = {0, 0};
    if (tid < 64) {
        int r = tid >> 1, o = (tid & 1) * 8;
        kgp = Kg + (size_t)r * KD + o;
        ksm[0] = s2u(&Ks[0][r][o]);
        ksm[1] = s2u(&Ks[1][r][o]);
    }
    // V tile: 64 rows x 64B = 256 chunks; 2 per thread
    const __nv_bfloat16* vgp[2];
    uint32_t vsm[2][2];
#pragma unroll
    for (int j = 0; j < 2; j++) {
        int idx = tid + j * 128;
        int r = idx >> 2, o = (idx & 3) * 8;
        vgp[j] = Vg + (size_t)r * SEQL + o;
        vsm[0][j] = s2u(&Vs[0][r][o]);
        vsm[1][j] = s2u(&Vs[1][r][o]);
    }

    // Q fragment: m16n8k16 A (rows g, g+8; dims 2tg,2tg+1, 8+2tg,8+2tg+1)
    const float SC = 0.25f * 1.44269504088896340736f;
    int qA = q0 + w * 16 + g;
    int qB = qA + 8;
    const float* qp0 = d_qbuf + (size_t)(b * QL + qA) * QD + h * KD;
    const float* qp1 = d_qbuf + (size_t)(b * QL + qB) * QD + h * KD;
    uint32_t qa[4];
    qa[0] = packbf(qp0[2 * tg] * SC,     qp0[2 * tg + 1] * SC);
    qa[1] = packbf(qp1[2 * tg] * SC,     qp1[2 * tg + 1] * SC);
    qa[2] = packbf(qp0[8 + 2 * tg] * SC, qp0[8 + 2 * tg + 1] * SC);
    qa[3] = packbf(qp1[8 + 2 * tg] * SC, qp1[8 + 2 * tg + 1] * SC);

    float acc[8][4];
#pragma unroll
    for (int i = 0; i < 8; i++)
#pragma unroll
        for (int j = 0; j < 4; j++) acc[i][j] = 0.0f;
    float l0 = 0.0f, l1 = 0.0f;

    // prefetch tile 0
    if (tid < 64) cpasync16(ksm[0], kgp);
#pragma unroll
    for (int j = 0; j < 2; j++) cpasync16(vsm[0][j], vgp[j]);
    CP_COMMIT();

    const int NT = SEQL / 32;
    for (int t = 0; t < NT; ++t) {
        if (t + 1 < NT) {
            int koff = (t + 1) * 32;
            int nbf = (t + 1) & 1;
            if (tid < 64) cpasync16(ksm[nbf], kgp + (size_t)koff * KD);
#pragma unroll
            for (int j = 0; j < 2; j++) cpasync16(vsm[nbf][j], vgp[j] + koff);
        }
        CP_COMMIT();
        CP_WAIT1();
        __syncthreads();

        const int bf = t & 1;
#pragma unroll
        for (int kg16 = 0; kg16 < 2; kg16++) {
            const int kr = kg16 * 16;
            // QK mma 1: keys kr..kr+7
            uint32_t kb0 = *(const uint32_t*)&Ks[bf][kr + g][2 * tg];
            uint32_t kb1 = *(const uint32_t*)&Ks[bf][kr + g][8 + 2 * tg];
            float c0 = 0.f, c1 = 0.f, c2 = 0.f, c3 = 0.f;
            mma_bf16(c0, c1, c2, c3, qa[0], qa[1], qa[2], qa[3], kb0, kb1);
            // QK mma 2: keys kr+8..kr+15
            uint32_t kb2 = *(const uint32_t*)&Ks[bf][kr + 8 + g][2 * tg];
            uint32_t kb3 = *(const uint32_t*)&Ks[bf][kr + 8 + g][8 + 2 * tg];
            float d0 = 0.f, d1 = 0.f, d2 = 0.f, d3 = 0.f;
            mma_bf16(d0, d1, d2, d3, qa[0], qa[1], qa[2], qa[3], kb2, kb3);

            float p00 = ex2(c0), p01 = ex2(c1), p02 = ex2(c2), p03 = ex2(c3);
            float p10 = ex2(d0), p11 = ex2(d1), p12 = ex2(d2), p13 = ex2(d3);
            l0 += (p00 + p01) + (p10 + p11);
            l1 += (p02 + p03) + (p12 + p13);

            // A-frag for AV (k = 16 keys, natural order)
            uint32_t a0 = packbf(p00, p01);   // row g,   keys kr+2tg, +1
            uint32_t a1 = packbf(p02, p03);   // row g+8
            uint32_t a2 = packbf(p10, p11);   // row g,   keys kr+8+2tg, +1
            uint32_t a3 = packbf(p12, p13);   // row g+8
#pragma unroll
            for (int nt = 0; nt < 8; nt++) {
                uint32_t vb0 = *(const uint32_t*)&Vs[bf][8 * nt + g][kr + 2 * tg];
                uint32_t vb1 = *(const uint32_t*)&Vs[bf][8 * nt + g][kr + 8 + 2 * tg];
                mma_bf16(acc[nt][0], acc[nt][1], acc[nt][2], acc[nt][3],
                         a0, a1, a2, a3, vb0, vb1);
            }
        }
        __syncthreads();
    }

    l0 += __shfl_xor_sync(0xffffffffu, l0, 1);
    l0 += __shfl_xor_sync(0xffffffffu, l0, 2);
    l1 += __shfl_xor_sync(0xffffffffu, l1, 1);
    l1 += __shfl_xor_sync(0xffffffffu, l1, 2);
    float r0 = 1.0f / l0, r1 = 1.0f / l1;

    float* zb = d_zbuf + (size_t)b * QL * COUT;
    int colA = qA & 511, hiA = qA >> 9;
    int colB = qB & 511, hiB = qB >> 9;
#pragma unroll
    for (int nt = 0; nt < 8; nt++) {
#pragma unroll
        for (int e = 0; e < 2; e++) {
            int d = 8 * nt + 2 * tg + e;
            zb[(size_t)(h * 128 + 2 * d + hiA) * COUT + colA] = acc[nt][e] * r0;
            zb[(size_t)(h * 128 + 2 * d + hiB) * COUT + colB] = acc[nt][2 + e] * r1;
        }
    }
}

// ---------------------------------------------------------------------------
// Launch
// ---------------------------------------------------------------------------
extern "C" void kernel_launch(void* const* d_in, const int* in_sizes, int n_in,
                              void* d_out, int out_size) {
    const float* x    = (const float*)d_in[0];
    const float* Wkv  = (const float*)d_in[1];
    const float* bkv  = (const float*)d_in[2];
    const float* gkv  = (const float*)d_in[3];
    const float* bekv = (const float*)d_in[4];
    const float* mkv  = (const float*)d_in[5];
    const float* vkv  = (const float*)d_in[6];
    const float* Wq   = (const float*)d_in[7];
    const float* bq   = (const float*)d_in[8];
    const float* gq   = (const float*)d_in[9];
    const float* beq  = (const float*)d_in[10];
    const float* mq   = (const float*)d_in[11];
    const float* vq   = (const float*)d_in[12];
    const float* Wp   = (const float*)d_in[13];
    const float* bp   = (const float*)d_in[14];
    const float* gp   = (const float*)d_in[15];
    const float* bep  = (const float*)d_in[16];
    const float* mp   = (const float*)d_in[17];
    const float* vp   = (const float*)d_in[18];
    float* out = (float*)d_out;

    fold_kernel<0><<<(CIN * KVD + 255) / 256, 256>>>(Wkv, bkv, gkv, bekv, mkv, vkv, CIN, KVD);
    fold_kernel<1><<<(CIN * QD + 255) / 256, 256>>>(Wq, bq, gq, beq, mq, vq, CIN, QD);
    fold_kernel<2><<<(COUT * COUT + 255) / 256, 256>>>(Wp, bp, gp, bep, mp, vp, COUT, COUT);

    // kv = BN(x @ Wkv + b): writes K (bf16) + V-transposed (bf16)
    tgemm_kernel<0, 0><<<dim3(KVD / 128, (BB * SEQL) / 128), 256>>>(x, nullptr, BB * SEQL, KVD, CIN);
    // q  = BN(xq @ Wq + b): fp32
    tgemm_kernel<1, 0><<<dim3(QD / 128, (BB * QL) / 128), 256>>>(x, nullptr, BB * QL, QD, CIN);
    // fused flash attention (bf16 mma) -> d_zbuf (TF-reshaped)
    attn_kernel<<<dim3(QL / 64, HH, BB), 128>>>();
    // out = BN(hardswish(Z) @ Wp + b): 3xTF32
    tgemm_kernel<2, 1><<<dim3(COUT / 128, (BB * QL) / 128), 256>>>(nullptr, out, BB * QL, COUT, COUT);
}